// round 5
// baseline (speedup 1.0000x reference)
#include <cuda_runtime.h>
#include <math.h>

#define G  4384
#define D  128
#define B  8
#define H1 64
#define NOUT 26
#define QB 8                  // queries per block in fused kernel (G/QB = 548 exact)
#define NT 512                // threads per block in fused kernel

// ---------------- device scratch ----------------
__device__ float4 g_P4[G];              // P'[k] = (W_in @ K^T)*scale*log2e
__device__ float  g_c[G];               // c'[k]
__device__ float  g_acc[B * G + B * D]; // [0,B*G): w column sums; then mean partials

__device__ __forceinline__ float ex2f(float x) {
    float e; asm("ex2.approx.f32 %0, %1;" : "=f"(e) : "f"(x)); return e;
}

// ---------------- K0: P[4,G], c[G], and zero g_acc ----------------
__global__ void k0_P(const float* __restrict__ Win, const float* __restrict__ bin,
                     const float* __restrict__ Kp) {
    int gtid = blockIdx.x * blockDim.x + threadIdx.x;
    if (gtid < B * G + B * D) g_acc[gtid] = 0.f;     // fused zero-init

    int warp = gtid >> 5;
    int lane = threadIdx.x & 31;
    if (warp >= G) return;
    const float S = 1.4426950408889634f * 0.08838834764831843f;  // log2e / sqrt(128)
    float a0 = 0.f, a1 = 0.f, a2 = 0.f, a3 = 0.f, cb = 0.f;
    const float* krow = Kp + (size_t)warp * D;
#pragma unroll
    for (int i = 0; i < 4; i++) {
        int d = lane + 32 * i;
        float kv = krow[d];
        a0 = fmaf(kv, Win[0 * D + d], a0);
        a1 = fmaf(kv, Win[1 * D + d], a1);
        a2 = fmaf(kv, Win[2 * D + d], a2);
        a3 = fmaf(kv, Win[3 * D + d], a3);
        cb = fmaf(kv, bin[d], cb);
    }
#pragma unroll
    for (int off = 16; off; off >>= 1) {
        a0 += __shfl_down_sync(0xffffffffu, a0, off);
        a1 += __shfl_down_sync(0xffffffffu, a1, off);
        a2 += __shfl_down_sync(0xffffffffu, a2, off);
        a3 += __shfl_down_sync(0xffffffffu, a3, off);
        cb += __shfl_down_sync(0xffffffffu, cb, off);
    }
    if (lane == 0) {
        g_P4[warp] = make_float4(a0 * S, a1 * S, a2 * S, a3 * S);
        g_c[warp]  = cb * S;
    }
}

// ---------------- K12: fused softmax row-norm + column-sum (exp evaluated ONCE) ----------------
// Pass A / Z-reduction identical to the proven R3 kernel. Pass B groups 4
// consecutive k per thread and issues ONE float4 atomicAdd (4x fewer RED ops).
extern __shared__ float k12_smem[];
__global__ void __launch_bounds__(NT, 1) k12(const float* __restrict__ mut) {
    float* sE   = k12_smem;             // G * 8 floats, row k at sE + k*8
    float* zbuf = k12_smem + G * QB;    // 16 warps * 8
    float* sr   = zbuf + (NT / 32) * QB;// 8 floats

    const int tid  = threadIdx.x;
    const int b    = blockIdx.y;
    const int q0   = blockIdx.x * QB;
    const int lane = tid & 31, warp = tid >> 5;

    // 8 query m-vectors
    float4 m[QB];
#pragma unroll
    for (int j = 0; j < QB; j++)
        m[j] = __ldg((const float4*)mut + (size_t)b * G + q0 + j);

    float z[QB];
#pragma unroll
    for (int j = 0; j < QB; j++) z[j] = 0.f;

    // ---- Pass A: scores -> exp -> smem, accumulate Z ----
    for (int k = tid; k < G; k += NT) {
        float4 p = __ldg(&g_P4[k]);
        float  c = __ldg(&g_c[k]);
        float e[QB];
#pragma unroll
        for (int j = 0; j < QB; j++) {
            float s = fmaf(m[j].x, p.x,
                      fmaf(m[j].y, p.y,
                      fmaf(m[j].z, p.z,
                      fmaf(m[j].w, p.w, c))));
            e[j] = ex2f(s);
            z[j] += e[j];
        }
        float4* row = (float4*)(sE + (size_t)k * QB);
        row[0] = make_float4(e[0], e[1], e[2], e[3]);
        row[1] = make_float4(e[4], e[5], e[6], e[7]);
    }

    // ---- Z reduction: within warp (disjoint k per lane), then across warps ----
#pragma unroll
    for (int j = 0; j < QB; j++) {
#pragma unroll
        for (int off = 16; off; off >>= 1)
            z[j] += __shfl_down_sync(0xffffffffu, z[j], off);
    }
    if (lane == 0) {
#pragma unroll
        for (int j = 0; j < QB; j++) zbuf[warp * QB + j] = z[j];
    }
    __syncthreads();
    if (tid < QB) {
        float Z = 0.f;
#pragma unroll
        for (int w = 0; w < NT / 32; w++) Z += zbuf[w * QB + tid];
        sr[tid] = 1.0f / Z;
    }
    __syncthreads();

    float r[QB];
#pragma unroll
    for (int j = 0; j < QB; j++) r[j] = sr[j];

    // ---- Pass B: column partial sums, 4 k per thread, one float4 RED ----
    float4* accv = (float4*)(g_acc + (size_t)b * G);   // G % 4 == 0, 16B-aligned
    for (int kq = tid; kq < G / 4; kq += NT) {
        float wv[4];
#pragma unroll
        for (int i = 0; i < 4; i++) {
            const float4* row = (const float4*)(sE + (size_t)(4 * kq + i) * QB);
            float4 a0 = row[0];
            float4 a1 = row[1];
            float wk = a0.x * r[0];
            wk = fmaf(a0.y, r[1], wk);
            wk = fmaf(a0.z, r[2], wk);
            wk = fmaf(a0.w, r[3], wk);
            wk = fmaf(a1.x, r[4], wk);
            wk = fmaf(a1.y, r[5], wk);
            wk = fmaf(a1.z, r[6], wk);
            wk = fmaf(a1.w, r[7], wk);
            wv[i] = wk;
        }
        atomicAdd(&accv[kq], make_float4(wv[0], wv[1], wv[2], wv[3]));
    }
}

// ---------------- K3a: mean partials = w @ V (all batches per block) ----------------
__global__ void k3a(const float* __restrict__ V) {
    int chunk = blockIdx.x;          // 0..136, 32 k each
    int d = threadIdx.x;             // 128
    int k0 = chunk * 32;
    float acc[B];
#pragma unroll
    for (int b = 0; b < B; b++) acc[b] = 0.f;
    for (int k = k0; k < k0 + 32; k++) {
        float v = __ldg(&V[(size_t)k * D + d]);
#pragma unroll
        for (int b = 0; b < B; b++) acc[b] = fmaf(g_acc[b * G + k], v, acc[b]);
    }
#pragma unroll
    for (int b = 0; b < B; b++) atomicAdd(&g_acc[B * G + b * D + d], acc[b]);
}

// ---------------- K3b: GELU MLP head (parallelized) ----------------
__global__ void k3b(const float* __restrict__ W1, const float* __restrict__ b1,
                    const float* __restrict__ W2, const float* __restrict__ b2,
                    float* __restrict__ out) {
    __shared__ float mean[D];
    __shared__ float h[H1];
    int b = blockIdx.x, tid = threadIdx.x;   // 256 threads
    if (tid < D) mean[tid] = g_acc[B * G + b * D + tid] * (1.0f / (float)G);
    __syncthreads();
    {   // h: 64 outputs x 4 threads each (all 256 threads, full warps)
        int hh = tid >> 2, part = tid & 3;
        float a = 0.f;
        for (int d = part; d < D; d += 4)
            a = fmaf(mean[d], __ldg(&W1[d * H1 + hh]), a);
        a += __shfl_down_sync(0xffffffffu, a, 2);
        a += __shfl_down_sync(0xffffffffu, a, 1);
        if (part == 0) {
            a += b1[hh];
            h[hh] = 0.5f * a * (1.0f + erff(a * 0.70710678118654752f));
        }
    }
    __syncthreads();
    if (tid < 128) {   // out: 26 outputs x 4 threads (full warps 0-3 active)
        int o = tid >> 2, part = tid & 3;
        int oc = o < NOUT ? o : NOUT - 1;
        float s = 0.f;
        for (int j = part; j < H1; j += 4)
            s = fmaf(h[j], __ldg(&W2[j * NOUT + oc]), s);
        s += __shfl_down_sync(0xffffffffu, s, 2);
        s += __shfl_down_sync(0xffffffffu, s, 1);
        if (part == 0 && o < NOUT) out[b * NOUT + o] = s + b2[o];
    }
}

// ---------------- launch ----------------
extern "C" void kernel_launch(void* const* d_in, const int* in_sizes, int n_in,
                              void* d_out, int out_size) {
    const float* mut = (const float*)d_in[0];   // [8,4384,4]
    const float* V   = (const float*)d_in[1];   // [4384,128]
    const float* Win = (const float*)d_in[2];   // [4,128]
    const float* bin = (const float*)d_in[3];   // [128]
    const float* Kp  = (const float*)d_in[4];   // [4384,128]
    const float* W1  = (const float*)d_in[5];   // [128,64]
    const float* b1  = (const float*)d_in[6];   // [64]
    const float* W2  = (const float*)d_in[7];   // [64,26]
    const float* b2  = (const float*)d_in[8];   // [26]
    float* out = (float*)d_out;                 // [8,26]
    (void)in_sizes; (void)n_in; (void)out_size;

    k0_P<<<548, 256>>>(Win, bin, Kp);           // 548*8 warps = 4384 = G (+ g_acc zeroing)

    size_t smemK12 = (size_t)G * QB * 4 + (NT / 32) * QB * 4 + QB * 4;  // 140,832 B
    cudaFuncSetAttribute(k12, cudaFuncAttributeMaxDynamicSharedMemorySize, (int)smemK12);
    k12<<<dim3(G / QB, B), NT, smemK12>>>(mut);

    k3a<<<137, D>>>(V);
    k3b<<<B, 256>>>(W1, b1, W2, b2, out);
}

// round 6
// speedup vs baseline: 1.7294x; 1.7294x over previous
#include <cuda_runtime.h>
#include <math.h>

#define G  4384
#define D  128
#define B  8
#define H1 64
#define NOUT 26
#define QB 8                  // queries per block in fused kernel (G/QB = 548 exact)
#define NT 512                // threads per block in fused kernel

// ---------------- device scratch ----------------
__device__ float4 g_P4[G];              // P'[k] = (W_in @ K^T)*scale*log2e
__device__ float  g_c[G];               // c'[k]
__device__ float  g_acc[B * G + B * D]; // [0,B*G): w column sums; then mean partials

__device__ __forceinline__ float ex2f(float x) {
    float e; asm("ex2.approx.f32 %0, %1;" : "=f"(e) : "f"(x)); return e;
}

// ---------------- K0: P[4,G], c[G], and zero g_acc ----------------
__global__ void k0_P(const float* __restrict__ Win, const float* __restrict__ bin,
                     const float* __restrict__ Kp) {
    int gtid = blockIdx.x * blockDim.x + threadIdx.x;
    if (gtid < B * G + B * D) g_acc[gtid] = 0.f;     // fused zero-init

    int warp = gtid >> 5;
    int lane = threadIdx.x & 31;
    if (warp >= G) return;
    const float S = 1.4426950408889634f * 0.08838834764831843f;  // log2e / sqrt(128)
    float a0 = 0.f, a1 = 0.f, a2 = 0.f, a3 = 0.f, cb = 0.f;
    const float* krow = Kp + (size_t)warp * D;
#pragma unroll
    for (int i = 0; i < 4; i++) {
        int d = lane + 32 * i;
        float kv = krow[d];
        a0 = fmaf(kv, Win[0 * D + d], a0);
        a1 = fmaf(kv, Win[1 * D + d], a1);
        a2 = fmaf(kv, Win[2 * D + d], a2);
        a3 = fmaf(kv, Win[3 * D + d], a3);
        cb = fmaf(kv, bin[d], cb);
    }
#pragma unroll
    for (int off = 16; off; off >>= 1) {
        a0 += __shfl_down_sync(0xffffffffu, a0, off);
        a1 += __shfl_down_sync(0xffffffffu, a1, off);
        a2 += __shfl_down_sync(0xffffffffu, a2, off);
        a3 += __shfl_down_sync(0xffffffffu, a3, off);
        cb += __shfl_down_sync(0xffffffffu, cb, off);
    }
    if (lane == 0) {
        g_P4[warp] = make_float4(a0 * S, a1 * S, a2 * S, a3 * S);
        g_c[warp]  = cb * S;
    }
}

// ---------------- K12: fused softmax row-norm + column-sum (exp evaluated ONCE) ----------------
// Same structure as the proven R3 kernel; only change: pass A software-
// pipelines the P/c loads one iteration ahead with a CLAMPED in-bounds index
// (no pads, no uninitialized values) to hide L2 latency.
extern __shared__ float k12_smem[];
__global__ void __launch_bounds__(NT, 1) k12(const float* __restrict__ mut) {
    float* sE   = k12_smem;             // G * 8 floats, row k at sE + k*8
    float* zbuf = k12_smem + G * QB;    // 16 warps * 8
    float* sr   = zbuf + (NT / 32) * QB;// 8 floats

    const int tid  = threadIdx.x;
    const int b    = blockIdx.y;
    const int q0   = blockIdx.x * QB;
    const int lane = tid & 31, warp = tid >> 5;

    // 8 query m-vectors
    float4 m[QB];
#pragma unroll
    for (int j = 0; j < QB; j++)
        m[j] = __ldg((const float4*)mut + (size_t)b * G + q0 + j);

    float z[QB];
#pragma unroll
    for (int j = 0; j < QB; j++) z[j] = 0.f;

    // ---- Pass A: scores -> exp -> smem, accumulate Z (1-deep clamped prefetch) ----
    int k = tid;                        // tid < NT <= G, always valid
    float4 p = __ldg(&g_P4[k]);
    float  c = __ldg(&g_c[k]);
    for (; k < G; k += NT) {
        int kn = (k + NT < G) ? (k + NT) : (G - 1);   // clamped: always in-bounds
        float4 pn = __ldg(&g_P4[kn]);
        float  cn = __ldg(&g_c[kn]);
        float e[QB];
#pragma unroll
        for (int j = 0; j < QB; j++) {
            float s = fmaf(m[j].x, p.x,
                      fmaf(m[j].y, p.y,
                      fmaf(m[j].z, p.z,
                      fmaf(m[j].w, p.w, c))));
            e[j] = ex2f(s);
            z[j] += e[j];
        }
        float4* row = (float4*)(sE + (size_t)k * QB);
        row[0] = make_float4(e[0], e[1], e[2], e[3]);
        row[1] = make_float4(e[4], e[5], e[6], e[7]);
        p = pn; c = cn;
    }

    // ---- Z reduction: within warp (disjoint k per lane), then across warps ----
#pragma unroll
    for (int j = 0; j < QB; j++) {
#pragma unroll
        for (int off = 16; off; off >>= 1)
            z[j] += __shfl_down_sync(0xffffffffu, z[j], off);
    }
    if (lane == 0) {
#pragma unroll
        for (int j = 0; j < QB; j++) zbuf[warp * QB + j] = z[j];
    }
    __syncthreads();
    if (tid < QB) {
        float Z = 0.f;
#pragma unroll
        for (int w = 0; w < NT / 32; w++) Z += zbuf[w * QB + tid];
        sr[tid] = 1.0f / Z;
    }
    __syncthreads();

    float r[QB];
#pragma unroll
    for (int j = 0; j < QB; j++) r[j] = sr[j];

    // ---- Pass B: column partial sums (R3-proven: one scalar RED per k) ----
    for (int kk = tid; kk < G; kk += NT) {
        const float4* row = (const float4*)(sE + (size_t)kk * QB);
        float4 a0 = row[0];
        float4 a1 = row[1];
        float wk = a0.x * r[0];
        wk = fmaf(a0.y, r[1], wk);
        wk = fmaf(a0.z, r[2], wk);
        wk = fmaf(a0.w, r[3], wk);
        wk = fmaf(a1.x, r[4], wk);
        wk = fmaf(a1.y, r[5], wk);
        wk = fmaf(a1.z, r[6], wk);
        wk = fmaf(a1.w, r[7], wk);
        atomicAdd(&g_acc[b * G + kk], wk);
    }
}

// ---------------- K3a: mean partials = w @ V (all batches per block) ----------------
__global__ void k3a(const float* __restrict__ V) {
    int chunk = blockIdx.x;          // 0..136, 32 k each
    int d = threadIdx.x;             // 128
    int k0 = chunk * 32;
    float acc[B];
#pragma unroll
    for (int b = 0; b < B; b++) acc[b] = 0.f;
    for (int k = k0; k < k0 + 32; k++) {
        float v = __ldg(&V[(size_t)k * D + d]);
#pragma unroll
        for (int b = 0; b < B; b++) acc[b] = fmaf(g_acc[b * G + k], v, acc[b]);
    }
#pragma unroll
    for (int b = 0; b < B; b++) atomicAdd(&g_acc[B * G + b * D + d], acc[b]);
}

// ---------------- K3b: GELU MLP head (parallelized) ----------------
__global__ void k3b(const float* __restrict__ W1, const float* __restrict__ b1,
                    const float* __restrict__ W2, const float* __restrict__ b2,
                    float* __restrict__ out) {
    __shared__ float mean[D];
    __shared__ float h[H1];
    int b = blockIdx.x, tid = threadIdx.x;   // 256 threads
    if (tid < D) mean[tid] = g_acc[B * G + b * D + tid] * (1.0f / (float)G);
    __syncthreads();
    {   // h: 64 outputs x 4 threads each (all 256 threads, full warps)
        int hh = tid >> 2, part = tid & 3;
        float a = 0.f;
        for (int d = part; d < D; d += 4)
            a = fmaf(mean[d], __ldg(&W1[d * H1 + hh]), a);
        a += __shfl_down_sync(0xffffffffu, a, 2);
        a += __shfl_down_sync(0xffffffffu, a, 1);
        if (part == 0) {
            a += b1[hh];
            h[hh] = 0.5f * a * (1.0f + erff(a * 0.70710678118654752f));
        }
    }
    __syncthreads();
    if (tid < 128) {   // out: 26 outputs x 4 threads (full warps 0-3 active)
        int o = tid >> 2, part = tid & 3;
        int oc = o < NOUT ? o : NOUT - 1;
        float s = 0.f;
        for (int j = part; j < H1; j += 4)
            s = fmaf(h[j], __ldg(&W2[j * NOUT + oc]), s);
        s += __shfl_down_sync(0xffffffffu, s, 2);
        s += __shfl_down_sync(0xffffffffu, s, 1);
        if (part == 0 && o < NOUT) out[b * NOUT + o] = s + b2[o];
    }
}

// ---------------- launch ----------------
extern "C" void kernel_launch(void* const* d_in, const int* in_sizes, int n_in,
                              void* d_out, int out_size) {
    const float* mut = (const float*)d_in[0];   // [8,4384,4]
    const float* V   = (const float*)d_in[1];   // [4384,128]
    const float* Win = (const float*)d_in[2];   // [4,128]
    const float* bin = (const float*)d_in[3];   // [128]
    const float* Kp  = (const float*)d_in[4];   // [4384,128]
    const float* W1  = (const float*)d_in[5];   // [128,64]
    const float* b1  = (const float*)d_in[6];   // [64]
    const float* W2  = (const float*)d_in[7];   // [64,26]
    const float* b2  = (const float*)d_in[8];   // [26]
    float* out = (float*)d_out;                 // [8,26]
    (void)in_sizes; (void)n_in; (void)out_size;

    k0_P<<<548, 256>>>(Win, bin, Kp);           // 548*8 warps = 4384 = G (+ g_acc zeroing)

    size_t smemK12 = (size_t)G * QB * 4 + (NT / 32) * QB * 4 + QB * 4;  // 140,832 B
    cudaFuncSetAttribute(k12, cudaFuncAttributeMaxDynamicSharedMemorySize, (int)smemK12);
    k12<<<dim3(G / QB, B), NT, smemK12>>>(mut);

    k3a<<<137, D>>>(V);
    k3b<<<B, 256>>>(W1, b1, W2, b2, out);
}